// round 15
// baseline (speedup 1.0000x reference)
#include <cuda_runtime.h>
#include <cuda_fp16.h>
#include <math.h>

// Problem constants (fixed by setup_inputs)
#define NN   100000
#define EE   3200000
#define DIN  512
#define DH   32
#define DC   40
#define PEPS 1e-5f
#define SCAN_B 1024
#define MAXBLK 128            // >= ceil(NN/SCAN_B)

// ---------------- scratch (device globals; no allocation allowed) ----------
__device__ int    g_deg[NN];
__device__ float  g_dinv[NN];
__device__ int    g_rowptr[NN + 1];
__device__ int    g_wpos[NN];
__device__ int    g_bsum[MAXBLK];
__device__ int    g_boff[MAXBLK + 1];
__device__ int    g_esrc[EE + NN];          // src only, grouped by dst
__device__ __half g_bufA[(size_t)NN * DH];
__device__ __half g_bufB[(size_t)NN * DH];
__device__ float  g_stats0[DH + 1];
__device__ float  g_stats1[DH + 1];
__device__ float  g_pn[DH + 1];             // means[32], scale

// ---------------- CSR build -------------------------------------------------
__global__ void k_zero(int n) {
    int i = blockIdx.x * blockDim.x + threadIdx.x;
    if (i < n) g_deg[i] = 0;
    if (i <= DH) { g_stats0[i] = 0.f; g_stats1[i] = 0.f; }
}

__global__ void k_hist(const int* __restrict__ ei, int E) {
    int e = blockIdx.x * blockDim.x + threadIdx.x;
    if (e < E) atomicAdd(&g_deg[ei[E + e]], 1);
}

// phase 1: per-block exclusive scan of (deg+1); also dinv
__global__ void __launch_bounds__(SCAN_B) k_scan1(int n) {
    __shared__ int sb[SCAN_B];
    int i = blockIdx.x * SCAN_B + threadIdx.x;
    int v = 0;
    if (i < n) {
        int d = g_deg[i];
        v = d + 1;
        g_dinv[i] = rsqrtf((float)(d + 1));
    }
    sb[threadIdx.x] = v;
    __syncthreads();
#pragma unroll
    for (int off = 1; off < SCAN_B; off <<= 1) {
        int t = (threadIdx.x >= off) ? sb[threadIdx.x - off] : 0;
        __syncthreads();
        sb[threadIdx.x] += t;
        __syncthreads();
    }
    if (i < n) g_rowptr[i] = sb[threadIdx.x] - v;     // within-block exclusive
    if (threadIdx.x == SCAN_B - 1) g_bsum[blockIdx.x] = sb[SCAN_B - 1];
}

// phase 2: parallel scan of block sums
__global__ void k_scan2(int nb) {
    __shared__ int sb[MAXBLK];
    int t = threadIdx.x;
    int v = (t < nb) ? g_bsum[t] : 0;
    sb[t] = v;
    __syncthreads();
#pragma unroll
    for (int off = 1; off < MAXBLK; off <<= 1) {
        int u = (t >= off) ? sb[t - off] : 0;
        __syncthreads();
        sb[t] += u;
        __syncthreads();
    }
    if (t < nb) g_boff[t] = sb[t] - v;
    if (t == nb - 1) g_boff[nb] = sb[t];
}

// phase 3: add offsets, produce rowptr + writable wpos
__global__ void __launch_bounds__(SCAN_B) k_scan3(int n, int nb) {
    int i = blockIdx.x * SCAN_B + threadIdx.x;
    if (i < n) {
        int rp = g_rowptr[i] + g_boff[blockIdx.x];
        g_rowptr[i] = rp;
        g_wpos[i]   = rp;
    }
    if (i == 0) g_rowptr[n] = g_boff[nb];
}

__global__ void k_scatter(const int* __restrict__ ei, int E, int n) {
    int e = blockIdx.x * blockDim.x + threadIdx.x;
    if (e < E) {
        int s = ei[e];
        int d = ei[E + e];
        int pos = atomicAdd(&g_wpos[d], 1);
        g_esrc[pos] = s;
    } else if (e < E + n) {
        int i   = e - E;
        int pos = atomicAdd(&g_wpos[i], 1);
        g_esrc[pos] = i;                 // self loop (norm = dinv[i]^2 arises naturally)
    }
}

// ---------------- GEMM0: bufA = x[n,512] @ W0[512,32] (fp16 out) -----------
__global__ void __launch_bounds__(256) k_gemm0(const float* __restrict__ x,
                                               const float* __restrict__ W0, int n) {
    __shared__ float As[64 * 32];
    __shared__ float WsT[32 * 36];
    int tid  = threadIdx.x;
    int lane = tid & 31;
    int warp = tid >> 5;
    int rb   = blockIdx.x * 64;

    float acc[8];
#pragma unroll
    for (int i = 0; i < 8; i++) acc[i] = 0.f;

    for (int kt = 0; kt < DIN; kt += 32) {
        {
            float4 wv = *(const float4*)&W0[kt * 32 + tid * 4];
            int kk = tid >> 3;
            int cb = (tid & 7) * 4;
            WsT[(cb + 0) * 36 + kk] = wv.x;
            WsT[(cb + 1) * 36 + kk] = wv.y;
            WsT[(cb + 2) * 36 + kk] = wv.z;
            WsT[(cb + 3) * 36 + kk] = wv.w;
        }
        {
            int row = tid >> 2;
            int seg = (tid & 3) * 8;
            int gr  = rb + row;
            float4 v0, v1;
            if (gr < n) {
                const float4* p = (const float4*)(x + (size_t)gr * DIN + kt + seg);
                v0 = p[0]; v1 = p[1];
            } else {
                v0 = make_float4(0.f, 0.f, 0.f, 0.f); v1 = v0;
            }
            *(float4*)&As[row * 32 + seg]     = v0;
            *(float4*)&As[row * 32 + seg + 4] = v1;
        }
        __syncthreads();
#pragma unroll
        for (int kk4 = 0; kk4 < 8; kk4++) {
            float4 w4 = *(const float4*)&WsT[lane * 36 + kk4 * 4];
#pragma unroll
            for (int i = 0; i < 8; i++) {
                float4 a4 = *(const float4*)&As[(warp * 8 + i) * 32 + kk4 * 4];
                acc[i] += a4.x * w4.x;
                acc[i] += a4.y * w4.y;
                acc[i] += a4.z * w4.z;
                acc[i] += a4.w * w4.w;
            }
        }
        __syncthreads();
    }
#pragma unroll
    for (int i = 0; i < 8; i++) {
        int gr = rb + warp * 8 + i;
        if (gr < n) g_bufA[(size_t)gr * DH + lane] = __float2half(acc[i]);
    }
}

// ---------------- fused aggregation kernels --------------------------------
// warp-per-node, lane-per-feature, grid-stride. 256thr = 8 warps/block.

__device__ __forceinline__ void block_stats(float cs, float ss, float* stats,
                                            int warp, int lane) {
    __shared__ float s_cs[8][32];
    __shared__ float s_ss[8];
    s_cs[warp][lane] = cs;
#pragma unroll
    for (int o = 16; o; o >>= 1) ss += __shfl_down_sync(0xffffffffu, ss, o);
    if (lane == 0) s_ss[warp] = ss;
    __syncthreads();
    if (warp == 0) {
        float c = 0.f;
#pragma unroll
        for (int w = 0; w < 8; w++) c += s_cs[w][lane];
        atomicAdd(&stats[lane], c);
        if (lane == 0) {
            float t = 0.f;
#pragma unroll
            for (int w = 0; w < 8; w++) t += s_ss[w];
            atomicAdd(&stats[DH], t);
        }
    }
}

// raw gather: acc += sum dinv[src] * h[src][lane]   (dinv[dst] factored out)
#define GATHER_RAW(HIN)                                                        \
    for (; p + 3 < pe; p += 4) {                                               \
        int s0 = g_esrc[p], s1 = g_esrc[p+1], s2 = g_esrc[p+2], s3 = g_esrc[p+3]; \
        float w0 = g_dinv[s0], w1 = g_dinv[s1], w2 = g_dinv[s2], w3 = g_dinv[s3]; \
        float h0 = __half2float(HIN[(size_t)s0 * DH + lane]);                  \
        float h1 = __half2float(HIN[(size_t)s1 * DH + lane]);                  \
        float h2 = __half2float(HIN[(size_t)s2 * DH + lane]);                  \
        float h3 = __half2float(HIN[(size_t)s3 * DH + lane]);                  \
        acc += h0 * w0 + h1 * w1 + h2 * w2 + h3 * w3;                          \
    }                                                                          \
    for (; p < pe; p++) {                                                      \
        int s0 = g_esrc[p];                                                    \
        acc += __half2float(HIN[(size_t)s0 * DH + lane]) * g_dinv[s0];         \
    }

// pn+relu gather: acc += sum dinv[src] * relu((h-mu)*sc)
#define GATHER_PN(HIN)                                                         \
    for (; p + 3 < pe; p += 4) {                                               \
        int s0 = g_esrc[p], s1 = g_esrc[p+1], s2 = g_esrc[p+2], s3 = g_esrc[p+3]; \
        float w0 = g_dinv[s0], w1 = g_dinv[s1], w2 = g_dinv[s2], w3 = g_dinv[s3]; \
        float h0 = fmaxf((__half2float(HIN[(size_t)s0 * DH + lane]) - mu) * sc, 0.f); \
        float h1 = fmaxf((__half2float(HIN[(size_t)s1 * DH + lane]) - mu) * sc, 0.f); \
        float h2 = fmaxf((__half2float(HIN[(size_t)s2 * DH + lane]) - mu) * sc, 0.f); \
        float h3 = fmaxf((__half2float(HIN[(size_t)s3 * DH + lane]) - mu) * sc, 0.f); \
        acc += h0 * w0 + h1 * w1 + h2 * w2 + h3 * w3;                          \
    }                                                                          \
    for (; p < pe; p++) {                                                      \
        int s0 = g_esrc[p];                                                    \
        float h0 = fmaxf((__half2float(HIN[(size_t)s0 * DH + lane]) - mu) * sc, 0.f); \
        acc += h0 * g_dinv[s0];                                                \
    }

// layer0: B = agg(A); stats0(B)
__global__ void __launch_bounds__(256) k_aggA(int n) {
    int lane = threadIdx.x & 31;
    int warp = threadIdx.x >> 5;
    int wglob = blockIdx.x * 8 + warp;
    int wtot  = gridDim.x * 8;
    float cs = 0.f, ss = 0.f;
    for (int node = wglob; node < n; node += wtot) {
        int p  = g_rowptr[node];
        int pe = g_rowptr[node + 1];
        float acc = 0.f;
        GATHER_RAW(g_bufA)
        acc *= g_dinv[node];
        g_bufB[(size_t)node * DH + lane] = __float2half(acc);
        cs += acc;
        ss += acc * acc;
    }
    block_stats(cs, ss, g_stats0, warp, lane);
}

// layer1: A = agg(pnrelu(B)) @ W1 ; stats1(A)
__global__ void __launch_bounds__(256) k_aggB(const float* __restrict__ W1, int n) {
    __shared__ float Ws[32 * 32];
    for (int i = threadIdx.x; i < 32 * 32; i += 256) Ws[i] = W1[i];
    __syncthreads();
    int lane = threadIdx.x & 31;
    int warp = threadIdx.x >> 5;
    int wglob = blockIdx.x * 8 + warp;
    int wtot  = gridDim.x * 8;
    float mu = g_pn[lane];
    float sc = g_pn[DH];
    float cs = 0.f, ss = 0.f;
    for (int node = wglob; node < n; node += wtot) {
        int p  = g_rowptr[node];
        int pe = g_rowptr[node + 1];
        float acc = 0.f;
        GATHER_PN(g_bufB)
        acc *= g_dinv[node];
        // epilogue: row = acc @ W1  (shfl broadcast)
        float o = 0.f;
#pragma unroll
        for (int k = 0; k < 32; k++)
            o += __shfl_sync(0xffffffffu, acc, k) * Ws[k * 32 + lane];
        g_bufA[(size_t)node * DH + lane] = __float2half(o);
        cs += o;
        ss += o * o;
    }
    block_stats(cs, ss, g_stats1, warp, lane);
}

// layer2: out = agg(pnrelu(A)) @ Wf + bf
__global__ void __launch_bounds__(256) k_aggC(const float* __restrict__ Wf,
                                              const float* __restrict__ bf,
                                              float* __restrict__ out, int n) {
    __shared__ float Ws[32 * DC];
    __shared__ float Bs[DC];
    for (int i = threadIdx.x; i < 32 * DC; i += 256) Ws[i] = Wf[i];
    if (threadIdx.x < DC) Bs[threadIdx.x] = bf[threadIdx.x];
    __syncthreads();
    int lane = threadIdx.x & 31;
    int warp = threadIdx.x >> 5;
    int wglob = blockIdx.x * 8 + warp;
    int wtot  = gridDim.x * 8;
    float mu = g_pn[lane];
    float sc = g_pn[DH];
    for (int node = wglob; node < n; node += wtot) {
        int p  = g_rowptr[node];
        int pe = g_rowptr[node + 1];
        float acc = 0.f;
        GATHER_PN(g_bufA)
        acc *= g_dinv[node];
        // epilogue: acc @ Wf (32->40) + bf
        float a0 = 0.f, a1 = 0.f;
#pragma unroll
        for (int k = 0; k < 32; k++) {
            float xv = __shfl_sync(0xffffffffu, acc, k);
            a0 += xv * Ws[k * DC + lane];
            if (lane < 8) a1 += xv * Ws[k * DC + 32 + lane];
        }
        out[(size_t)node * DC + lane] = a0 + Bs[lane];
        if (lane < 8) out[(size_t)node * DC + 32 + lane] = a1 + Bs[32 + lane];
    }
}

// ---------------- PairNorm finalize -----------------------------------------
__global__ void k_pnfin(int sel, int n) {
    const float* st = sel ? g_stats1 : g_stats0;
    int l = threadIdx.x;               // 32 threads
    float m = st[l] / (float)n;
    g_pn[l] = m;
    float mm = m * m;
#pragma unroll
    for (int o = 16; o; o >>= 1) mm += __shfl_down_sync(0xffffffffu, mm, o);
    if (l == 0) {
        float var = st[DH] / (float)n - mm;
        g_pn[DH] = rsqrtf(PEPS + var);
    }
}

// ---------------- launch ----------------------------------------------------
extern "C" void kernel_launch(void* const* d_in, const int* in_sizes, int n_in,
                              void* d_out, int out_size) {
    const float* x  = (const float*)d_in[0];
    const int*   ei = (const int*)d_in[1];   // int32 (JAX x64 disabled)
    const float* W0 = (const float*)d_in[2];
    // d_in[3]=b0, d_in[5]=b1 cancel exactly under PairNorm mean subtraction
    const float* W1 = (const float*)d_in[4];
    const float* Wf = (const float*)d_in[6];
    const float* bf = (const float*)d_in[7];
    float*       out = (float*)d_out;

    const int E = in_sizes[1] / 2;
    const int n = in_sizes[0] / DIN;

    const int nbS  = (n + SCAN_B - 1) / SCAN_B;     // scan blocks
    const int AGGB = 148 * 8;                       // grid-stride agg blocks

    // CSR build: A + I with symmetric gcn_norm (norm factored as dinv*dinv)
    k_zero   <<<(n + 255) / 256, 256>>>(n);
    k_hist   <<<(E + 255) / 256, 256>>>(ei, E);
    k_scan1  <<<nbS, SCAN_B>>>(n);
    k_scan2  <<<1, MAXBLK>>>(nbS);
    k_scan3  <<<nbS, SCAN_B>>>(n, nbS);
    k_scatter<<<(E + n + 255) / 256, 256>>>(ei, E, n);

    // forward
    k_gemm0  <<<(n + 63) / 64, 256>>>(x, W0, n);    // x @ W0 -> A (fp16)
    k_aggA   <<<AGGB, 256>>>(n);                    // agg(A) -> B, stats0
    k_pnfin  <<<1, 32>>>(0, n);
    k_aggB   <<<AGGB, 256>>>(W1, n);                // agg(pnrelu(B)) @ W1 -> A, stats1
    k_pnfin  <<<1, 32>>>(1, n);
    k_aggC   <<<AGGB, 256>>>(Wf, bf, out, n);       // agg(pnrelu(A)) @ Wf + bf -> out
}

// round 16
// speedup vs baseline: 1.1010x; 1.1010x over previous
#include <cuda_runtime.h>
#include <cuda_fp16.h>
#include <math.h>

// Problem constants (fixed by setup_inputs)
#define NN   100000
#define EE   3200000
#define DIN  512
#define DH   32
#define DC   40
#define PEPS 1e-5f
#define SCAN_B 1024
#define MAXBLK 128            // >= ceil(NN/SCAN_B)

// ---------------- scratch (device globals; no allocation allowed) ----------
__device__ int     g_deg[NN];
__device__ float   g_dinv[NN];
__device__ int     g_rowptr[NN + 1];
__device__ int     g_wpos[NN];
__device__ int     g_bsum[MAXBLK];
__device__ int     g_boff[MAXBLK + 1];
__device__ int2    g_edges[EE + NN];        // {src, bits(norm)} grouped by dst
__device__ __half2 g_bufA[(size_t)NN * 16]; // fp16 features, half2-aligned
__device__ __half2 g_bufB[(size_t)NN * 16];
__device__ float   g_stats0[DH + 1];
__device__ float   g_stats1[DH + 1];
__device__ float   g_pn[DH + 1];            // means[32], scale

// ---------------- CSR build -------------------------------------------------
__global__ void k_zero(int n) {
    int i = blockIdx.x * blockDim.x + threadIdx.x;
    if (i < n) g_deg[i] = 0;
    if (i <= DH) { g_stats0[i] = 0.f; g_stats1[i] = 0.f; }
}

__global__ void k_hist(const int* __restrict__ ei, int E) {
    int e = blockIdx.x * blockDim.x + threadIdx.x;
    if (e < E) atomicAdd(&g_deg[ei[E + e]], 1);
}

// phase 1: per-block exclusive scan of (deg+1); also dinv
__global__ void __launch_bounds__(SCAN_B) k_scan1(int n) {
    __shared__ int sb[SCAN_B];
    int i = blockIdx.x * SCAN_B + threadIdx.x;
    int v = 0;
    if (i < n) {
        int d = g_deg[i];
        v = d + 1;
        g_dinv[i] = rsqrtf((float)(d + 1));
    }
    sb[threadIdx.x] = v;
    __syncthreads();
#pragma unroll
    for (int off = 1; off < SCAN_B; off <<= 1) {
        int t = (threadIdx.x >= off) ? sb[threadIdx.x - off] : 0;
        __syncthreads();
        sb[threadIdx.x] += t;
        __syncthreads();
    }
    if (i < n) g_rowptr[i] = sb[threadIdx.x] - v;
    if (threadIdx.x == SCAN_B - 1) g_bsum[blockIdx.x] = sb[SCAN_B - 1];
}

// phase 2: parallel scan of block sums
__global__ void k_scan2(int nb) {
    __shared__ int sb[MAXBLK];
    int t = threadIdx.x;
    int v = (t < nb) ? g_bsum[t] : 0;
    sb[t] = v;
    __syncthreads();
#pragma unroll
    for (int off = 1; off < MAXBLK; off <<= 1) {
        int u = (t >= off) ? sb[t - off] : 0;
        __syncthreads();
        sb[t] += u;
        __syncthreads();
    }
    if (t < nb) g_boff[t] = sb[t] - v;
    if (t == nb - 1) g_boff[nb] = sb[t];
}

// phase 3: add offsets, produce rowptr + writable wpos
__global__ void __launch_bounds__(SCAN_B) k_scan3(int n, int nb) {
    int i = blockIdx.x * SCAN_B + threadIdx.x;
    if (i < n) {
        int rp = g_rowptr[i] + g_boff[blockIdx.x];
        g_rowptr[i] = rp;
        g_wpos[i]   = rp;
    }
    if (i == 0) g_rowptr[n] = g_boff[nb];
}

__global__ void k_scatter(const int* __restrict__ ei, int E, int n) {
    int e = blockIdx.x * blockDim.x + threadIdx.x;
    if (e < E) {
        int s = ei[e];
        int d = ei[E + e];
        int pos = atomicAdd(&g_wpos[d], 1);
        g_edges[pos] = make_int2(s, __float_as_int(g_dinv[s] * g_dinv[d]));
    } else if (e < E + n) {
        int i   = e - E;
        float v = g_dinv[i];
        int pos = atomicAdd(&g_wpos[i], 1);
        g_edges[pos] = make_int2(i, __float_as_int(v * v));
    }
}

// ---------------- GEMM0: bufA = x[n,512] @ W0[512,32] (fp16 out) -----------
__global__ void __launch_bounds__(256) k_gemm0(const float* __restrict__ x,
                                               const float* __restrict__ W0, int n) {
    __shared__ float As[64 * 32];
    __shared__ float WsT[32 * 36];
    int tid  = threadIdx.x;
    int lane = tid & 31;
    int warp = tid >> 5;
    int rb   = blockIdx.x * 64;

    float acc[8];
#pragma unroll
    for (int i = 0; i < 8; i++) acc[i] = 0.f;

    for (int kt = 0; kt < DIN; kt += 32) {
        {
            float4 wv = *(const float4*)&W0[kt * 32 + tid * 4];
            int kk = tid >> 3;
            int cb = (tid & 7) * 4;
            WsT[(cb + 0) * 36 + kk] = wv.x;
            WsT[(cb + 1) * 36 + kk] = wv.y;
            WsT[(cb + 2) * 36 + kk] = wv.z;
            WsT[(cb + 3) * 36 + kk] = wv.w;
        }
        {
            int row = tid >> 2;
            int seg = (tid & 3) * 8;
            int gr  = rb + row;
            float4 v0, v1;
            if (gr < n) {
                const float4* p = (const float4*)(x + (size_t)gr * DIN + kt + seg);
                v0 = p[0]; v1 = p[1];
            } else {
                v0 = make_float4(0.f, 0.f, 0.f, 0.f); v1 = v0;
            }
            *(float4*)&As[row * 32 + seg]     = v0;
            *(float4*)&As[row * 32 + seg + 4] = v1;
        }
        __syncthreads();
#pragma unroll
        for (int kk4 = 0; kk4 < 8; kk4++) {
            float4 w4 = *(const float4*)&WsT[lane * 36 + kk4 * 4];
#pragma unroll
            for (int i = 0; i < 8; i++) {
                float4 a4 = *(const float4*)&As[(warp * 8 + i) * 32 + kk4 * 4];
                acc[i] += a4.x * w4.x;
                acc[i] += a4.y * w4.y;
                acc[i] += a4.z * w4.z;
                acc[i] += a4.w * w4.w;
            }
        }
        __syncthreads();
    }
    __half* A = (__half*)g_bufA;
#pragma unroll
    for (int i = 0; i < 8; i++) {
        int gr = rb + warp * 8 + i;
        if (gr < n) A[(size_t)gr * DH + lane] = __float2half(acc[i]);
    }
}

// ---------------- fused aggregation -----------------------------------------
// warp-per-node, grid-stride. Edges consumed in chunks of 32 (coalesced record
// load into lanes, shfl-broadcast). Two edges processed per h-gather: lanes
// 0-15 read edge A's half2 row, lanes 16-31 edge B's. Lane holds features
// {2c, 2c+1} (c = lane&15); a 4-shfl epilogue converts to lane-per-feature.

__device__ __forceinline__ void block_stats(float cs, float ss, float* stats,
                                            int warp, int lane) {
    __shared__ float s_cs[8][32];
    __shared__ float s_ss[8];
    s_cs[warp][lane] = cs;
#pragma unroll
    for (int o = 16; o; o >>= 1) ss += __shfl_down_sync(0xffffffffu, ss, o);
    if (lane == 0) s_ss[warp] = ss;
    __syncthreads();
    if (warp == 0) {
        float c = 0.f;
#pragma unroll
        for (int w = 0; w < 8; w++) c += s_cs[w][lane];
        atomicAdd(&stats[lane], c);
        if (lane == 0) {
            float t = 0.f;
#pragma unroll
            for (int w = 0; w < 8; w++) t += s_ss[w];
            atomicAdd(&stats[DH], t);
        }
    }
}

// PN==0: raw gather.  PN==1: relu((h-mu)*sc) applied to gathered values.
template <int PN>
__device__ __forceinline__ float gather_node(const __half2* __restrict__ hin,
                                             int p, int pe, int lane,
                                             float2 mu2, float sc) {
    int col  = lane & 15;
    int hsel = lane >> 4;              // 0: even edge of pair, 1: odd edge
    float ax = 0.f, ay = 0.f;

    while (p + 32 <= pe) {
        int2 rec = g_edges[p + lane];  // coalesced 256B
#pragma unroll
        for (int j = 0; j < 16; j++) {
            int idx  = 2 * j + hsel;
            int s    = __shfl_sync(0xffffffffu, rec.x, idx);
            float w  = __int_as_float(__shfl_sync(0xffffffffu, rec.y, idx));
            float2 h = __half22float2(hin[(size_t)s * 16 + col]);
            if (PN) {
                h.x = fmaxf((h.x - mu2.x) * sc, 0.f);
                h.y = fmaxf((h.y - mu2.y) * sc, 0.f);
            }
            ax += h.x * w;
            ay += h.y * w;
        }
        p += 32;
    }
    int rem = pe - p;
    if (rem > 0) {
        int2 rec = (lane < rem) ? g_edges[p + lane] : make_int2(0, 0);
        for (int j = 0; 2 * j < rem; j++) {
            int idx  = 2 * j + hsel;   // idx may equal rem (odd rem): that lane's w==0
            int s    = __shfl_sync(0xffffffffu, rec.x, idx);
            float w  = __int_as_float(__shfl_sync(0xffffffffu, rec.y, idx));
            float2 h = __half22float2(hin[(size_t)s * 16 + col]);
            if (PN) {
                h.x = fmaxf((h.x - mu2.x) * sc, 0.f);
                h.y = fmaxf((h.y - mu2.y) * sc, 0.f);
            }
            ax += h.x * w;
            ay += h.y * w;
        }
    }
    // combine edge-pair halves, then redistribute to lane-per-feature
    ax += __shfl_xor_sync(0xffffffffu, ax, 16);
    ay += __shfl_xor_sync(0xffffffffu, ay, 16);
    float vx = __shfl_sync(0xffffffffu, ax, lane >> 1);
    float vy = __shfl_sync(0xffffffffu, ay, lane >> 1);
    return (lane & 1) ? vy : vx;       // lane f holds feature f
}

// layer0: B = agg(A); stats0(B)
__global__ void __launch_bounds__(256) k_aggA(int n) {
    int lane = threadIdx.x & 31;
    int warp = threadIdx.x >> 5;
    int wglob = blockIdx.x * 8 + warp;
    int wtot  = gridDim.x * 8;
    __half* Bo = (__half*)g_bufB;
    float cs = 0.f, ss = 0.f;
    for (int node = wglob; node < n; node += wtot) {
        float val = gather_node<0>(g_bufA, g_rowptr[node], g_rowptr[node + 1],
                                   lane, make_float2(0.f, 0.f), 0.f);
        Bo[(size_t)node * DH + lane] = __float2half(val);
        cs += val;
        ss += val * val;
    }
    block_stats(cs, ss, g_stats0, warp, lane);
}

// layer1: A = agg(pnrelu(B)) @ W1 ; stats1(A)
__global__ void __launch_bounds__(256) k_aggB(const float* __restrict__ W1, int n) {
    __shared__ float Ws[32 * 32];
    for (int i = threadIdx.x; i < 32 * 32; i += 256) Ws[i] = W1[i];
    __syncthreads();
    int lane = threadIdx.x & 31;
    int warp = threadIdx.x >> 5;
    int wglob = blockIdx.x * 8 + warp;
    int wtot  = gridDim.x * 8;
    int col   = lane & 15;
    float2 mu2 = make_float2(g_pn[2 * col], g_pn[2 * col + 1]);
    float  sc  = g_pn[DH];
    __half* Ao = (__half*)g_bufA;
    float cs = 0.f, ss = 0.f;
    for (int node = wglob; node < n; node += wtot) {
        float val = gather_node<1>(g_bufB, g_rowptr[node], g_rowptr[node + 1],
                                   lane, mu2, sc);
        float o = 0.f;
#pragma unroll
        for (int k = 0; k < 32; k++)
            o += __shfl_sync(0xffffffffu, val, k) * Ws[k * 32 + lane];
        Ao[(size_t)node * DH + lane] = __float2half(o);
        cs += o;
        ss += o * o;
    }
    block_stats(cs, ss, g_stats1, warp, lane);
}

// layer2: out = agg(pnrelu(A)) @ Wf + bf
__global__ void __launch_bounds__(256) k_aggC(const float* __restrict__ Wf,
                                              const float* __restrict__ bf,
                                              float* __restrict__ out, int n) {
    __shared__ float Ws[32 * DC];
    __shared__ float Bs[DC];
    for (int i = threadIdx.x; i < 32 * DC; i += 256) Ws[i] = Wf[i];
    if (threadIdx.x < DC) Bs[threadIdx.x] = bf[threadIdx.x];
    __syncthreads();
    int lane = threadIdx.x & 31;
    int warp = threadIdx.x >> 5;
    int wglob = blockIdx.x * 8 + warp;
    int wtot  = gridDim.x * 8;
    int col   = lane & 15;
    float2 mu2 = make_float2(g_pn[2 * col], g_pn[2 * col + 1]);
    float  sc  = g_pn[DH];
    for (int node = wglob; node < n; node += wtot) {
        float val = gather_node<1>(g_bufA, g_rowptr[node], g_rowptr[node + 1],
                                   lane, mu2, sc);
        float a0 = 0.f, a1 = 0.f;
#pragma unroll
        for (int k = 0; k < 32; k++) {
            float xv = __shfl_sync(0xffffffffu, val, k);
            a0 += xv * Ws[k * DC + lane];
            if (lane < 8) a1 += xv * Ws[k * DC + 32 + lane];
        }
        out[(size_t)node * DC + lane] = a0 + Bs[lane];
        if (lane < 8) out[(size_t)node * DC + 32 + lane] = a1 + Bs[32 + lane];
    }
}

// ---------------- PairNorm finalize -----------------------------------------
__global__ void k_pnfin(int sel, int n) {
    const float* st = sel ? g_stats1 : g_stats0;
    int l = threadIdx.x;               // 32 threads
    float m = st[l] / (float)n;
    g_pn[l] = m;
    float mm = m * m;
#pragma unroll
    for (int o = 16; o; o >>= 1) mm += __shfl_down_sync(0xffffffffu, mm, o);
    if (l == 0) {
        float var = st[DH] / (float)n - mm;
        g_pn[DH] = rsqrtf(PEPS + var);
    }
}

// ---------------- launch ----------------------------------------------------
extern "C" void kernel_launch(void* const* d_in, const int* in_sizes, int n_in,
                              void* d_out, int out_size) {
    const float* x  = (const float*)d_in[0];
    const int*   ei = (const int*)d_in[1];   // int32 (JAX x64 disabled)
    const float* W0 = (const float*)d_in[2];
    // d_in[3]=b0, d_in[5]=b1 cancel exactly under PairNorm mean subtraction
    const float* W1 = (const float*)d_in[4];
    const float* Wf = (const float*)d_in[6];
    const float* bf = (const float*)d_in[7];
    float*       out = (float*)d_out;

    const int E = in_sizes[1] / 2;
    const int n = in_sizes[0] / DIN;

    const int nbS  = (n + SCAN_B - 1) / SCAN_B;
    const int AGGB = 148 * 8;

    // CSR build: A + I with symmetric gcn_norm
    k_zero   <<<(n + 255) / 256, 256>>>(n);
    k_hist   <<<(E + 255) / 256, 256>>>(ei, E);
    k_scan1  <<<nbS, SCAN_B>>>(n);
    k_scan2  <<<1, MAXBLK>>>(nbS);
    k_scan3  <<<nbS, SCAN_B>>>(n, nbS);
    k_scatter<<<(E + n + 255) / 256, 256>>>(ei, E, n);

    // forward
    k_gemm0  <<<(n + 63) / 64, 256>>>(x, W0, n);    // x @ W0 -> A (fp16)
    k_aggA   <<<AGGB, 256>>>(n);                    // agg(A) -> B, stats0
    k_pnfin  <<<1, 32>>>(0, n);
    k_aggB   <<<AGGB, 256>>>(W1, n);                // agg(pnrelu(B)) @ W1 -> A, stats1
    k_pnfin  <<<1, 32>>>(1, n);
    k_aggC   <<<AGGB, 256>>>(Wf, bf, out, n);       // agg(pnrelu(A)) @ Wf + bf -> out
}

// round 17
// speedup vs baseline: 1.3862x; 1.2590x over previous
#include <cuda_runtime.h>
#include <cuda_fp16.h>
#include <math.h>
#include <stdint.h>

// Problem constants (fixed by setup_inputs)
#define NN   100000
#define EE   3200000
#define DIN  512
#define DH   32
#define DC   40
#define PEPS 1e-5f
#define SCAN_B 1024
#define MAXBLK 128            // >= ceil(NN/SCAN_B)

// ---------------- scratch (device globals; no allocation allowed) ----------
__device__ int     g_deg[NN];
__device__ float   g_dinv[NN];
__device__ int     g_rowptr[NN + 1];
__device__ int     g_wpos[NN];
__device__ int     g_bsum[MAXBLK];
__device__ int     g_boff[MAXBLK + 1];
__device__ int2    g_edges[EE + NN];        // {src, bits(norm)} grouped by dst
__device__ __half2 g_bufA[(size_t)NN * 16]; // fp16 features, half2-aligned
__device__ __half2 g_bufB[(size_t)NN * 16];
__device__ float   g_stats0[DH + 1];
__device__ float   g_stats1[DH + 1];
__device__ float   g_pn[DH + 1];            // means[32], scale

// ---------------- CSR build -------------------------------------------------
__global__ void k_zero(int n) {
    int i = blockIdx.x * blockDim.x + threadIdx.x;
    if (i < n) g_deg[i] = 0;
    if (i <= DH) { g_stats0[i] = 0.f; g_stats1[i] = 0.f; }
}

__global__ void k_hist(const int* __restrict__ ei, int E) {
    int e = blockIdx.x * blockDim.x + threadIdx.x;
    if (e < E) atomicAdd(&g_deg[ei[E + e]], 1);
}

// phase 1: per-block exclusive scan of (deg+1); also dinv
__global__ void __launch_bounds__(SCAN_B) k_scan1(int n) {
    __shared__ int sb[SCAN_B];
    int i = blockIdx.x * SCAN_B + threadIdx.x;
    int v = 0;
    if (i < n) {
        int d = g_deg[i];
        v = d + 1;
        g_dinv[i] = rsqrtf((float)(d + 1));
    }
    sb[threadIdx.x] = v;
    __syncthreads();
#pragma unroll
    for (int off = 1; off < SCAN_B; off <<= 1) {
        int t = (threadIdx.x >= off) ? sb[threadIdx.x - off] : 0;
        __syncthreads();
        sb[threadIdx.x] += t;
        __syncthreads();
    }
    if (i < n) g_rowptr[i] = sb[threadIdx.x] - v;
    if (threadIdx.x == SCAN_B - 1) g_bsum[blockIdx.x] = sb[SCAN_B - 1];
}

// phase 2: parallel scan of block sums
__global__ void k_scan2(int nb) {
    __shared__ int sb[MAXBLK];
    int t = threadIdx.x;
    int v = (t < nb) ? g_bsum[t] : 0;
    sb[t] = v;
    __syncthreads();
#pragma unroll
    for (int off = 1; off < MAXBLK; off <<= 1) {
        int u = (t >= off) ? sb[t - off] : 0;
        __syncthreads();
        sb[t] += u;
        __syncthreads();
    }
    if (t < nb) g_boff[t] = sb[t] - v;
    if (t == nb - 1) g_boff[nb] = sb[t];
}

// phase 3: add offsets, produce rowptr + writable wpos
__global__ void __launch_bounds__(SCAN_B) k_scan3(int n, int nb) {
    int i = blockIdx.x * SCAN_B + threadIdx.x;
    if (i < n) {
        int rp = g_rowptr[i] + g_boff[blockIdx.x];
        g_rowptr[i] = rp;
        g_wpos[i]   = rp;
    }
    if (i == 0) g_rowptr[n] = g_boff[nb];
}

__global__ void k_scatter(const int* __restrict__ ei, int E, int n) {
    int e = blockIdx.x * blockDim.x + threadIdx.x;
    if (e < E) {
        int s = ei[e];
        int d = ei[E + e];
        int pos = atomicAdd(&g_wpos[d], 1);
        g_edges[pos] = make_int2(s, __float_as_int(g_dinv[s] * g_dinv[d]));
    } else if (e < E + n) {
        int i   = e - E;
        float v = g_dinv[i];
        int pos = atomicAdd(&g_wpos[i], 1);
        g_edges[pos] = make_int2(i, __float_as_int(v * v));
    }
}

// ---------------- GEMM0 (tf32 tensor cores): bufA = x @ W0, fp16 out -------
// Block: 256 thr = 8 warps; tile 256 rows x 32 cols; warp = m32 x n32.
// K chunked by 32, register prefetch. smem: A stride 36 (conflict-free frags),
// W chunk stride 40 (conflict-free frags).

__device__ __forceinline__ uint32_t f2tf(float f) {
    uint32_t r;
    asm("cvt.rna.tf32.f32 %0, %1;" : "=r"(r) : "f"(f));
    return r;
}

__global__ void __launch_bounds__(256) k_gemm0(const float* __restrict__ x,
                                               const float* __restrict__ W0, int n) {
    __shared__ uint32_t sA[256 * 36];   // [row][k] tf32, stride 36
    __shared__ uint32_t sW[32 * 40];    // [k][n]  tf32, stride 40

    int tid  = threadIdx.x;
    int lane = tid & 31;
    int warp = tid >> 5;
    int rb   = blockIdx.x * 256;

    int rowL = tid >> 3;                // 0..31 (loader row / W k-row)
    int mseg = (tid & 7) * 4;           // 16B segment within 32-wide chunk

    int grp = lane >> 2;                // 0..7
    int qid = lane & 3;                 // 0..3
    int wr  = warp * 32;                // warp row base within tile

    float c[2][4][4];
#pragma unroll
    for (int f = 0; f < 2; f++)
#pragma unroll
        for (int nt = 0; nt < 4; nt++)
#pragma unroll
            for (int i = 0; i < 4; i++) c[f][nt][i] = 0.f;

    const float4 z4 = make_float4(0.f, 0.f, 0.f, 0.f);

    // prologue: load + stage chunk 0
    {
        float4 pa[8], pw;
#pragma unroll
        for (int j = 0; j < 8; j++) {
            int gr = rb + rowL + j * 32;
            pa[j] = (gr < n) ? *(const float4*)&x[(size_t)gr * DIN + mseg] : z4;
        }
        pw = *(const float4*)&W0[(size_t)rowL * DH + mseg];
#pragma unroll
        for (int j = 0; j < 8; j++) {
            int r = rowL + j * 32;
            uint4 t = make_uint4(f2tf(pa[j].x), f2tf(pa[j].y), f2tf(pa[j].z), f2tf(pa[j].w));
            *(uint4*)&sA[r * 36 + mseg] = t;
        }
        {
            uint4 t = make_uint4(f2tf(pw.x), f2tf(pw.y), f2tf(pw.z), f2tf(pw.w));
            *(uint4*)&sW[rowL * 40 + mseg] = t;
        }
        __syncthreads();
    }

    for (int kc = 0; kc < 16; kc++) {
        // prefetch next chunk into registers
        float4 na[8], nw;
        bool more = (kc + 1 < 16);
        if (more) {
            int kb = (kc + 1) * 32;
#pragma unroll
            for (int j = 0; j < 8; j++) {
                int gr = rb + rowL + j * 32;
                na[j] = (gr < n) ? *(const float4*)&x[(size_t)gr * DIN + kb + mseg] : z4;
            }
            nw = *(const float4*)&W0[(size_t)(kb + rowL) * DH + mseg];
        }

        // compute on staged chunk: 4 k-steps of k8
#pragma unroll
        for (int ks = 0; ks < 4; ks++) {
            int k0 = ks * 8;
            uint32_t a[2][4], b[4][2];
#pragma unroll
            for (int f = 0; f < 2; f++) {
                int r = wr + f * 16 + grp;
                a[f][0] = sA[r * 36 + k0 + qid];
                a[f][1] = sA[(r + 8) * 36 + k0 + qid];
                a[f][2] = sA[r * 36 + k0 + 4 + qid];
                a[f][3] = sA[(r + 8) * 36 + k0 + 4 + qid];
            }
#pragma unroll
            for (int nt = 0; nt < 4; nt++) {
                b[nt][0] = sW[(k0 + qid) * 40 + nt * 8 + grp];
                b[nt][1] = sW[(k0 + 4 + qid) * 40 + nt * 8 + grp];
            }
#pragma unroll
            for (int f = 0; f < 2; f++)
#pragma unroll
                for (int nt = 0; nt < 4; nt++)
                    asm volatile(
                        "mma.sync.aligned.m16n8k8.row.col.f32.tf32.tf32.f32 "
                        "{%0,%1,%2,%3}, {%4,%5,%6,%7}, {%8,%9}, {%0,%1,%2,%3};"
                        : "+f"(c[f][nt][0]), "+f"(c[f][nt][1]),
                          "+f"(c[f][nt][2]), "+f"(c[f][nt][3])
                        : "r"(a[f][0]), "r"(a[f][1]), "r"(a[f][2]), "r"(a[f][3]),
                          "r"(b[nt][0]), "r"(b[nt][1]));
        }
        __syncthreads();

        if (more) {
#pragma unroll
            for (int j = 0; j < 8; j++) {
                int r = rowL + j * 32;
                uint4 t = make_uint4(f2tf(na[j].x), f2tf(na[j].y), f2tf(na[j].z), f2tf(na[j].w));
                *(uint4*)&sA[r * 36 + mseg] = t;
            }
            {
                uint4 t = make_uint4(f2tf(nw.x), f2tf(nw.y), f2tf(nw.z), f2tf(nw.w));
                *(uint4*)&sW[rowL * 40 + mseg] = t;
            }
            __syncthreads();
        }
    }

    // epilogue: fp16 half2 stores
    __half* A = (__half*)g_bufA;
#pragma unroll
    for (int f = 0; f < 2; f++) {
#pragma unroll
        for (int nt = 0; nt < 4; nt++) {
            int r0 = rb + wr + f * 16 + grp;
            int cc = nt * 8 + qid * 2;
            if (r0 < n)
                *(__half2*)&A[(size_t)r0 * DH + cc] =
                    __floats2half2_rn(c[f][nt][0], c[f][nt][1]);
            if (r0 + 8 < n)
                *(__half2*)&A[(size_t)(r0 + 8) * DH + cc] =
                    __floats2half2_rn(c[f][nt][2], c[f][nt][3]);
        }
    }
}

// ---------------- fused aggregation -----------------------------------------
// warp-per-node, grid-stride. Edges consumed in chunks of 32 (coalesced record
// load into lanes, shfl-broadcast). Two edges processed per h-gather: lanes
// 0-15 read edge A's half2 row, lanes 16-31 edge B's.

__device__ __forceinline__ void block_stats(float cs, float ss, float* stats,
                                            int warp, int lane) {
    __shared__ float s_cs[8][32];
    __shared__ float s_ss[8];
    s_cs[warp][lane] = cs;
#pragma unroll
    for (int o = 16; o; o >>= 1) ss += __shfl_down_sync(0xffffffffu, ss, o);
    if (lane == 0) s_ss[warp] = ss;
    __syncthreads();
    if (warp == 0) {
        float c = 0.f;
#pragma unroll
        for (int w = 0; w < 8; w++) c += s_cs[w][lane];
        atomicAdd(&stats[lane], c);
        if (lane == 0) {
            float t = 0.f;
#pragma unroll
            for (int w = 0; w < 8; w++) t += s_ss[w];
            atomicAdd(&stats[DH], t);
        }
    }
}

// PN==0: raw gather.  PN==1: relu((h-mu)*sc) applied to gathered values.
template <int PN>
__device__ __forceinline__ float gather_node(const __half2* __restrict__ hin,
                                             int p, int pe, int lane,
                                             float2 mu2, float sc) {
    int col  = lane & 15;
    int hsel = lane >> 4;              // 0: even edge of pair, 1: odd edge
    float ax = 0.f, ay = 0.f;

    while (p + 32 <= pe) {
        int2 rec = g_edges[p + lane];  // coalesced 256B
#pragma unroll
        for (int j = 0; j < 16; j++) {
            int idx  = 2 * j + hsel;
            int s    = __shfl_sync(0xffffffffu, rec.x, idx);
            float w  = __int_as_float(__shfl_sync(0xffffffffu, rec.y, idx));
            float2 h = __half22float2(hin[(size_t)s * 16 + col]);
            if (PN) {
                h.x = fmaxf((h.x - mu2.x) * sc, 0.f);
                h.y = fmaxf((h.y - mu2.y) * sc, 0.f);
            }
            ax += h.x * w;
            ay += h.y * w;
        }
        p += 32;
    }
    int rem = pe - p;
    if (rem > 0) {
        int2 rec = (lane < rem) ? g_edges[p + lane] : make_int2(0, 0);
        for (int j = 0; 2 * j < rem; j++) {
            int idx  = 2 * j + hsel;   // idx may equal rem (odd rem): that lane's w==0
            int s    = __shfl_sync(0xffffffffu, rec.x, idx);
            float w  = __int_as_float(__shfl_sync(0xffffffffu, rec.y, idx));
            float2 h = __half22float2(hin[(size_t)s * 16 + col]);
            if (PN) {
                h.x = fmaxf((h.x - mu2.x) * sc, 0.f);
                h.y = fmaxf((h.y - mu2.y) * sc, 0.f);
            }
            ax += h.x * w;
            ay += h.y * w;
        }
    }
    // combine edge-pair halves, then redistribute to lane-per-feature
    ax += __shfl_xor_sync(0xffffffffu, ax, 16);
    ay += __shfl_xor_sync(0xffffffffu, ay, 16);
    float vx = __shfl_sync(0xffffffffu, ax, lane >> 1);
    float vy = __shfl_sync(0xffffffffu, ay, lane >> 1);
    return (lane & 1) ? vy : vx;       // lane f holds feature f
}

// layer0: B = agg(A); stats0(B)
__global__ void __launch_bounds__(256) k_aggA(int n) {
    int lane = threadIdx.x & 31;
    int warp = threadIdx.x >> 5;
    int wglob = blockIdx.x * 8 + warp;
    int wtot  = gridDim.x * 8;
    __half* Bo = (__half*)g_bufB;
    float cs = 0.f, ss = 0.f;
    for (int node = wglob; node < n; node += wtot) {
        float val = gather_node<0>(g_bufA, g_rowptr[node], g_rowptr[node + 1],
                                   lane, make_float2(0.f, 0.f), 0.f);
        Bo[(size_t)node * DH + lane] = __float2half(val);
        cs += val;
        ss += val * val;
    }
    block_stats(cs, ss, g_stats0, warp, lane);
}

// layer1: A = agg(pnrelu(B)) @ W1 ; stats1(A)
__global__ void __launch_bounds__(256) k_aggB(const float* __restrict__ W1, int n) {
    __shared__ float Ws[32 * 32];
    for (int i = threadIdx.x; i < 32 * 32; i += 256) Ws[i] = W1[i];
    __syncthreads();
    int lane = threadIdx.x & 31;
    int warp = threadIdx.x >> 5;
    int wglob = blockIdx.x * 8 + warp;
    int wtot  = gridDim.x * 8;
    int col   = lane & 15;
    float2 mu2 = make_float2(g_pn[2 * col], g_pn[2 * col + 1]);
    float  sc  = g_pn[DH];
    __half* Ao = (__half*)g_bufA;
    float cs = 0.f, ss = 0.f;
    for (int node = wglob; node < n; node += wtot) {
        float val = gather_node<1>(g_bufB, g_rowptr[node], g_rowptr[node + 1],
                                   lane, mu2, sc);
        float o = 0.f;
#pragma unroll
        for (int k = 0; k < 32; k++)
            o += __shfl_sync(0xffffffffu, val, k) * Ws[k * 32 + lane];
        Ao[(size_t)node * DH + lane] = __float2half(o);
        cs += o;
        ss += o * o;
    }
    block_stats(cs, ss, g_stats1, warp, lane);
}

// layer2: out = agg(pnrelu(A)) @ Wf + bf
__global__ void __launch_bounds__(256) k_aggC(const float* __restrict__ Wf,
                                              const float* __restrict__ bf,
                                              float* __restrict__ out, int n) {
    __shared__ float Ws[32 * DC];
    __shared__ float Bs[DC];
    for (int i = threadIdx.x; i < 32 * DC; i += 256) Ws[i] = Wf[i];
    if (threadIdx.x < DC) Bs[threadIdx.x] = bf[threadIdx.x];
    __syncthreads();
    int lane = threadIdx.x & 31;
    int warp = threadIdx.x >> 5;
    int wglob = blockIdx.x * 8 + warp;
    int wtot  = gridDim.x * 8;
    int col   = lane & 15;
    float2 mu2 = make_float2(g_pn[2 * col], g_pn[2 * col + 1]);
    float  sc  = g_pn[DH];
    for (int node = wglob; node < n; node += wtot) {
        float val = gather_node<1>(g_bufA, g_rowptr[node], g_rowptr[node + 1],
                                   lane, mu2, sc);
        float a0 = 0.f, a1 = 0.f;
#pragma unroll
        for (int k = 0; k < 32; k++) {
            float xv = __shfl_sync(0xffffffffu, val, k);
            a0 += xv * Ws[k * DC + lane];
            if (lane < 8) a1 += xv * Ws[k * DC + 32 + lane];
        }
        out[(size_t)node * DC + lane] = a0 + Bs[lane];
        if (lane < 8) out[(size_t)node * DC + 32 + lane] = a1 + Bs[32 + lane];
    }
}

// ---------------- PairNorm finalize -----------------------------------------
__global__ void k_pnfin(int sel, int n) {
    const float* st = sel ? g_stats1 : g_stats0;
    int l = threadIdx.x;               // 32 threads
    float m = st[l] / (float)n;
    g_pn[l] = m;
    float mm = m * m;
#pragma unroll
    for (int o = 16; o; o >>= 1) mm += __shfl_down_sync(0xffffffffu, mm, o);
    if (l == 0) {
        float var = st[DH] / (float)n - mm;
        g_pn[DH] = rsqrtf(PEPS + var);
    }
}

// ---------------- launch ----------------------------------------------------
extern "C" void kernel_launch(void* const* d_in, const int* in_sizes, int n_in,
                              void* d_out, int out_size) {
    const float* x  = (const float*)d_in[0];
    const int*   ei = (const int*)d_in[1];   // int32 (JAX x64 disabled)
    const float* W0 = (const float*)d_in[2];
    // d_in[3]=b0, d_in[5]=b1 cancel exactly under PairNorm mean subtraction
    const float* W1 = (const float*)d_in[4];
    const float* Wf = (const float*)d_in[6];
    const float* bf = (const float*)d_in[7];
    float*       out = (float*)d_out;

    const int E = in_sizes[1] / 2;
    const int n = in_sizes[0] / DIN;

    const int nbS  = (n + SCAN_B - 1) / SCAN_B;
    const int AGGB = 148 * 8;

    // CSR build: A + I with symmetric gcn_norm
    k_zero   <<<(n + 255) / 256, 256>>>(n);
    k_hist   <<<(E + 255) / 256, 256>>>(ei, E);
    k_scan1  <<<nbS, SCAN_B>>>(n);
    k_scan2  <<<1, MAXBLK>>>(nbS);
    k_scan3  <<<nbS, SCAN_B>>>(n, nbS);
    k_scatter<<<(E + n + 255) / 256, 256>>>(ei, E, n);

    // forward
    k_gemm0  <<<(n + 255) / 256, 256>>>(x, W0, n);  // x @ W0 -> A (tf32 MMA, fp16 out)
    k_aggA   <<<AGGB, 256>>>(n);                    // agg(A) -> B, stats0
    k_pnfin  <<<1, 32>>>(0, n);
    k_aggB   <<<AGGB, 256>>>(W1, n);                // agg(pnrelu(B)) @ W1 -> A, stats1
    k_pnfin  <<<1, 32>>>(1, n);
    k_aggC   <<<AGGB, 256>>>(Wf, bf, out, n);       // agg(pnrelu(A)) @ Wf + bf -> out
}